// round 5
// baseline (speedup 1.0000x reference)
#include <cuda_runtime.h>

#define BB 512
#define DD 1024
#define HH 512
#define CC 4
#define DCH 8
#define KK (DD / DCH)       // 128 chunks
#define NSEG 4
#define HITER (HH / NSEG)   // 128 per hseg

// P'[k][h][b] = 0.5*(c + sum_{j<8k} x[b,j]W[h,j]); +BB pad for prefetch overrun
__device__ float g_P[((size_t)KK * HH + 1) * BB];      // ~134 MB, streamed
// xT[d][b] = 0.5 * x[b][d]
__device__ float g_XT[(size_t)DD * BB];
// vb[d][c] = bias[d][c] + 0.5 * sum_h V[h][d][c]
__device__ float g_VB[DD * CC];

__device__ __forceinline__ float tanh_fast(float a) {
    float th;
    asm("tanh.approx.f32 %0, %1;" : "=f"(th) : "f"(a));
    return th;
}

// ---------------- Phase 0a: vb = bias + 0.5 * sum_h V ----------------
__global__ __launch_bounds__(128) void nade_vb(
    const float* __restrict__ V, const float* __restrict__ bias)
{
    const int i = blockIdx.x * 128 + threadIdx.x;   // 0..4095
    float s = 0.f;
#pragma unroll 8
    for (int h = 0; h < HH; h++)
        s += __ldg(&V[(size_t)h * (DD * CC) + i]);
    g_VB[i] = fmaf(0.5f, s, __ldg(&bias[i]));
}

// ---------------- Phase 0b: xT[d][b] = 0.5 * x[b][d] ----------------
__global__ __launch_bounds__(256) void nade_xt(const float* __restrict__ x)
{
    __shared__ float tile[32][33];
    const int b0 = blockIdx.x * 32;
    const int d0 = blockIdx.y * 32;
    const int tx = threadIdx.x;       // 0..31
    const int ty = threadIdx.y;       // 0..7
#pragma unroll
    for (int r = 0; r < 4; r++)
        tile[ty + 8 * r][tx] = __ldg(&x[(size_t)(b0 + ty + 8 * r) * DD + d0 + tx]);
    __syncthreads();
#pragma unroll
    for (int r = 0; r < 4; r++)
        g_XT[(size_t)(d0 + ty + 8 * r) * BB + b0 + tx] = 0.5f * tile[tx][ty + 8 * r];
}

// ---------------- Phase 1: prefix GEMM, snapshots every 8 j ----------------
// grid (HH/8, BB/32), block 128: bl = tid&31 (b), hg = tid>>5 -> 2 h each.
__global__ __launch_bounds__(128) void nade_phase1(
    const float* __restrict__ W, const float* __restrict__ cvec)
{
    const int tid = threadIdx.x;
    const int bl = tid & 31;
    const int hg = tid >> 5;                 // 0..3
    const int h0 = blockIdx.x * 8 + hg * 2;  // 2 consecutive h
    const int b = blockIdx.y * 32 + bl;

    float acc0 = 0.5f * __ldg(&cvec[h0]);
    float acc1 = 0.5f * __ldg(&cvec[h0 + 1]);

    const float4* w0 = (const float4*)(W + (size_t)h0 * DD);
    const float4* w1 = (const float4*)(W + (size_t)(h0 + 1) * DD);

    for (int k = 0; k < KK; k++) {
        float* Pk = g_P + ((size_t)k * HH + h0) * BB + b;
        Pk[0] = acc0;
        Pk[BB] = acc1;

        float xv[DCH];
#pragma unroll
        for (int j = 0; j < DCH; j++)
            xv[j] = g_XT[(size_t)(k * DCH + j) * BB + b];         // coalesced

#pragma unroll
        for (int q = 0; q < 2; q++) {
            float4 wa = __ldg(&w0[k * 2 + q]);                    // warp-uniform
            float4 wb = __ldg(&w1[k * 2 + q]);
            acc0 = fmaf(xv[4 * q + 0], wa.x, acc0);
            acc0 = fmaf(xv[4 * q + 1], wa.y, acc0);
            acc0 = fmaf(xv[4 * q + 2], wa.z, acc0);
            acc0 = fmaf(xv[4 * q + 3], wa.w, acc0);
            acc1 = fmaf(xv[4 * q + 0], wb.x, acc1);
            acc1 = fmaf(xv[4 * q + 1], wb.y, acc1);
            acc1 = fmaf(xv[4 * q + 2], wb.z, acc1);
            acc1 = fmaf(xv[4 * q + 3], wb.w, acc1);
        }
    }
}

// ---------------- Phase 2: per-chunk sequential NADE ----------------
// grid (KK, BB/64), block 256: bl = tid&63 (b), hseg = tid>>6 (0..3).
// Thread: one b, 8 d, 128 h. No catch-up (P is at DCH=8 granularity).
__global__ __launch_bounds__(256, 3) void nade_phase2(
    const float* __restrict__ V, const float* __restrict__ W,
    float* __restrict__ out)
{
    __shared__ float ws[HH][DCH];                 // 16 KB: W[h][d0:d0+8]
    __shared__ float red[NSEG - 1][DCH * CC][64]; // 24 KB

    const int k = blockIdx.x;
    const int b0 = blockIdx.y * 64;
    const int tid = threadIdx.x;
    const int bl = tid & 63;
    const int hseg = tid >> 6;
    const int b = b0 + bl;
    const int d0 = k * DCH;

    // stage W slice: 512 rows x 32B (2 float4 per row)
    for (int i = tid; i < HH * 2; i += 256) {
        const int hh = i >> 1, q = i & 1;
        float4 wv = __ldg((const float4*)(W + (size_t)hh * DD + d0) + q);
        *(float4*)&ws[hh][q * 4] = wv;
    }

    // preload 0.5*x[b, d0:d0+8] (coalesced from xT)
    float xv[DCH];
#pragma unroll
    for (int j = 0; j < DCH; j++)
        xv[j] = g_XT[(size_t)(d0 + j) * BB + b];

    float acc[DCH][CC];
#pragma unroll
    for (int d = 0; d < DCH; d++)
#pragma unroll
        for (int c = 0; c < CC; c++) acc[d][c] = 0.f;

    __syncthreads();

    const int hstart = hseg * HITER;
    const float* Pp = g_P + ((size_t)k * HH + hstart) * BB + b;
    const float4* Vp = (const float4*)V + ((size_t)hstart * DD + d0);

    float a_next = __ldg(Pp);
    for (int it = 0; it < HITER; ++it) {
        float a = a_next;
        Pp += BB;
        a_next = __ldg(Pp);                         // pad row protects last read
        const float* wr = ws[hstart + it];
#pragma unroll
        for (int q = 0; q < 2; q++) {
            float4 w4 = *(const float4*)(wr + 4 * q);   // broadcast LDS.128
            float wq[4] = {w4.x, w4.y, w4.z, w4.w};
#pragma unroll
            for (int r = 0; r < 4; r++) {
                const int d = 4 * q + r;
                float4 v = __ldg(Vp + d);               // warp-uniform
                float th = tanh_fast(a);
                acc[d][0] = fmaf(th, v.x, acc[d][0]);
                acc[d][1] = fmaf(th, v.y, acc[d][1]);
                acc[d][2] = fmaf(th, v.z, acc[d][2]);
                acc[d][3] = fmaf(th, v.w, acc[d][3]);
                a = fmaf(xv[d], wq[r], a);              // halved-prefix advance
            }
        }
        Vp += DD;
    }

    if (hseg > 0) {
#pragma unroll
        for (int d = 0; d < DCH; d++)
#pragma unroll
            for (int c = 0; c < CC; c++)
                red[hseg - 1][d * CC + c][bl] = acc[d][c];
    }
    __syncthreads();

    if (hseg == 0) {
        float* yout = out + (size_t)b * (DD * CC) + (size_t)d0 * CC;
        float* pout = yout + (size_t)BB * DD * CC;
#pragma unroll
        for (int d = 0; d < DCH; d++) {
            const float4 vb = *(const float4*)&g_VB[(d0 + d) * CC];
            float l[4];
#pragma unroll
            for (int c = 0; c < CC; c++) {
                float s = acc[d][c] + red[0][d * CC + c][bl]
                        + red[1][d * CC + c][bl] + red[2][d * CC + c][bl];
                l[c] = fmaf(0.5f, s, ((const float*)&vb)[c]);
            }

            *(float4*)(yout + d * CC) = make_float4(l[0], l[1], l[2], l[3]);

            float m = fmaxf(fmaxf(l[0], l[1]), fmaxf(l[2], l[3]));
            float s = __expf(l[0] - m) + __expf(l[1] - m) +
                      __expf(l[2] - m) + __expf(l[3] - m);
            float lse = m + __logf(s);
            *(float4*)(pout + d * CC) =
                make_float4(l[0] - lse, l[1] - lse, l[2] - lse, l[3] - lse);
        }
    }
}

extern "C" void kernel_launch(void* const* d_in, const int* in_sizes, int n_in,
                              void* d_out, int out_size) {
    const float* x    = (const float*)d_in[0];
    const float* V    = (const float*)d_in[1];
    const float* bias = (const float*)d_in[2];
    const float* W    = (const float*)d_in[3];
    const float* cvec = (const float*)d_in[4];
    float* out = (float*)d_out;

    nade_vb<<<(DD * CC) / 128, 128>>>(V, bias);
    nade_xt<<<dim3(BB / 32, DD / 32), dim3(32, 8)>>>(x);
    nade_phase1<<<dim3(HH / 8, BB / 32), 128>>>(W, cvec);
    nade_phase2<<<dim3(KK, BB / 64), 256>>>(V, W, out);
}